// round 11
// baseline (speedup 1.0000x reference)
#include <cuda_runtime.h>
#include <cuda_bf16.h>
#include <math.h>

typedef unsigned long long ull;

// Problem constants
#define BB   256          // batch
#define TT   512          // seq len
#define HH   256          // hidden
#define GG   1024         // 4*H gates
#define CC   128          // classes
#define MM   (BB*TT)      // 131072 rows for input GEMMs

// ---------------- scratch (device globals; no allocs allowed) ----------------
__device__ float g_GX[(size_t)MM * GG];      // 512 MB  pregates, layout [b][t][gate]
__device__ float g_HBUF[(size_t)MM * HH];    // 128 MB  layer-0 hidden states
__device__ float g_H0[BB * HH];
__device__ float g_H1[BB * HH];
__device__ unsigned int g_flag[128 * 32];    // per-CTA barrier flags, 128B lines

// ---------------- packed f32x2 helpers (Blackwell FFMA2 path) ----------------
__device__ __forceinline__ ull pack2(float x, float y) {
    ull r;
    asm("mov.b64 %0, {%1, %2};" : "=l"(r) : "f"(x), "f"(y));
    return r;
}
__device__ __forceinline__ float2 unpack2(ull v) {
    float2 r;
    asm("mov.b64 {%0, %1}, %2;" : "=f"(r.x), "=f"(r.y) : "l"(v));
    return r;
}
__device__ __forceinline__ ull ffma2x(ull a, ull b, ull c) {
    ull d;
    asm("fma.rn.f32x2 %0, %1, %2, %3;" : "=l"(d) : "l"(a), "l"(b), "l"(c));
    return d;
}

// fast activations (error ~1e-6, well inside 1e-3 budget)
__device__ __forceinline__ float fsigm(float x) {
    float e = __expf(-x);
    return __fdividef(1.0f, 1.0f + e);
}
__device__ __forceinline__ float ftanh(float x) {
    float e = __expf(2.0f * x);           // overflow -> inf -> result 1 (correct)
    return 1.0f - __fdividef(2.0f, e + 1.0f);
}

__device__ __forceinline__ unsigned int ld_acquire_u(const unsigned int* p) {
    unsigned int v;
    asm volatile("ld.global.acquire.gpu.u32 %0, [%1];" : "=r"(v) : "l"(p) : "memory");
    return v;
}
__device__ __forceinline__ void st_release_u(unsigned int* p, unsigned int v) {
    asm volatile("st.global.release.gpu.u32 [%0], %1;" :: "l"(p), "r"(v) : "memory");
}

// ---------------- big GEMM:  Cout[m,n] = sum_k A[m,k]*W[n,k] + b1[n] + b2[n] --
// A: [MM,256] row-major (x, or g_HBUF), W: [1024,256] row-major.
// Tiles: BM=128, BN=64, BK=16, 256 threads, thread tile 8x4 (4 m-pairs x 4 n).
// Double-buffered smem; Bs stored as DUPLICATED (b,b) f32x2 pairs so the
// inner loop has zero packs: 4 LDS.128 + 16 FFMA2 per k.
// Also resets the persist-kernel barrier flags (block (0,0)) so no separate
// reset launch is needed.
__global__ void __launch_bounds__(256) gemm_gx(const float* __restrict__ Aext,
                                               int useExt,
                                               const float* __restrict__ W,
                                               const float* __restrict__ b1,
                                               const float* __restrict__ b2) {
    __shared__ __align__(16) float As[2][16][128];
    __shared__ __align__(16) ull  Bsd[2][16][64];

    const int tid = threadIdx.x;

    // fold barrier-flag reset into this kernel (stream order guarantees
    // completion before lstm_persist launches)
    if (blockIdx.x == 0 && blockIdx.y == 0 && tid < 128)
        g_flag[tid * 32] = 0u;

    const float* __restrict__ A = useExt ? Aext : g_HBUF;
    float* __restrict__ Cout = g_GX;

    const int ty = tid >> 4;          // 0..15  (m group of 8)
    const int tx = tid & 15;          // 0..15  (n group of 4)
    const int bm0 = blockIdx.y * 128;
    const int bn0 = blockIdx.x * 64;

    const int a_row0 = tid >> 2;              // 0..63
    const int a_kg   = (tid & 3) * 4;
    const int b_row  = tid >> 2;
    const int b_kg   = (tid & 3) * 4;

    ull acc[4][4];
    #pragma unroll
    for (int i = 0; i < 4; i++)
        #pragma unroll
        for (int j = 0; j < 4; j++) acc[i][j] = 0ull;

    {
        #pragma unroll
        for (int i = 0; i < 2; i++) {
            int row = a_row0 + i * 64;
            float4 v = *(const float4*)&A[(size_t)(bm0 + row) * 256 + a_kg];
            As[0][a_kg + 0][row] = v.x; As[0][a_kg + 1][row] = v.y;
            As[0][a_kg + 2][row] = v.z; As[0][a_kg + 3][row] = v.w;
        }
        float4 v = *(const float4*)&W[(size_t)(bn0 + b_row) * 256 + b_kg];
        Bsd[0][b_kg + 0][b_row] = pack2(v.x, v.x);
        Bsd[0][b_kg + 1][b_row] = pack2(v.y, v.y);
        Bsd[0][b_kg + 2][b_row] = pack2(v.z, v.z);
        Bsd[0][b_kg + 3][b_row] = pack2(v.w, v.w);
    }
    __syncthreads();

    int buf = 0;
    for (int k0 = 0; k0 < 256; k0 += 16) {
        float4 pa0, pa1, pb;
        const bool more = (k0 + 16) < 256;
        if (more) {
            pa0 = *(const float4*)&A[(size_t)(bm0 + a_row0) * 256 + k0 + 16 + a_kg];
            pa1 = *(const float4*)&A[(size_t)(bm0 + a_row0 + 64) * 256 + k0 + 16 + a_kg];
            pb  = *(const float4*)&W[(size_t)(bn0 + b_row) * 256 + k0 + 16 + b_kg];
        }

        #pragma unroll
        for (int k = 0; k < 16; k++) {
            const ull* ap = (const ull*)&As[buf][k][ty * 8];
            ull a0 = ap[0], a1 = ap[1], a2 = ap[2], a3 = ap[3];
            const ulonglong2* bpk = (const ulonglong2*)&Bsd[buf][k][0];
            ulonglong2 b01 = bpk[tx * 2];
            ulonglong2 b23 = bpk[tx * 2 + 1];
            acc[0][0] = ffma2x(a0, b01.x, acc[0][0]);
            acc[1][0] = ffma2x(a1, b01.x, acc[1][0]);
            acc[2][0] = ffma2x(a2, b01.x, acc[2][0]);
            acc[3][0] = ffma2x(a3, b01.x, acc[3][0]);
            acc[0][1] = ffma2x(a0, b01.y, acc[0][1]);
            acc[1][1] = ffma2x(a1, b01.y, acc[1][1]);
            acc[2][1] = ffma2x(a2, b01.y, acc[2][1]);
            acc[3][1] = ffma2x(a3, b01.y, acc[3][1]);
            acc[0][2] = ffma2x(a0, b23.x, acc[0][2]);
            acc[1][2] = ffma2x(a1, b23.x, acc[1][2]);
            acc[2][2] = ffma2x(a2, b23.x, acc[2][2]);
            acc[3][2] = ffma2x(a3, b23.x, acc[3][2]);
            acc[0][3] = ffma2x(a0, b23.y, acc[0][3]);
            acc[1][3] = ffma2x(a1, b23.y, acc[1][3]);
            acc[2][3] = ffma2x(a2, b23.y, acc[2][3]);
            acc[3][3] = ffma2x(a3, b23.y, acc[3][3]);
        }

        if (more) {
            int nb = buf ^ 1;
            As[nb][a_kg + 0][a_row0] = pa0.x; As[nb][a_kg + 1][a_row0] = pa0.y;
            As[nb][a_kg + 2][a_row0] = pa0.z; As[nb][a_kg + 3][a_row0] = pa0.w;
            As[nb][a_kg + 0][a_row0 + 64] = pa1.x; As[nb][a_kg + 1][a_row0 + 64] = pa1.y;
            As[nb][a_kg + 2][a_row0 + 64] = pa1.z; As[nb][a_kg + 3][a_row0 + 64] = pa1.w;
            Bsd[nb][b_kg + 0][b_row] = pack2(pb.x, pb.x);
            Bsd[nb][b_kg + 1][b_row] = pack2(pb.y, pb.y);
            Bsd[nb][b_kg + 2][b_row] = pack2(pb.z, pb.z);
            Bsd[nb][b_kg + 3][b_row] = pack2(pb.w, pb.w);
            __syncthreads();
            buf = nb;
        }
    }

    float4 b1v = *(const float4*)&b1[bn0 + tx * 4];
    float4 b2v = *(const float4*)&b2[bn0 + tx * 4];
    float4 bias = make_float4(b1v.x + b2v.x, b1v.y + b2v.y,
                              b1v.z + b2v.z, b1v.w + b2v.w);
    #pragma unroll
    for (int i = 0; i < 4; i++) {
        float2 q0 = unpack2(acc[i][0]);
        float2 q1 = unpack2(acc[i][1]);
        float2 q2 = unpack2(acc[i][2]);
        float2 q3 = unpack2(acc[i][3]);
        size_t r0 = (size_t)(bm0 + ty * 8 + 2 * i);
        float4 v0 = make_float4(q0.x + bias.x, q1.x + bias.y, q2.x + bias.z, q3.x + bias.w);
        float4 v1 = make_float4(q0.y + bias.x, q1.y + bias.y, q2.y + bias.z, q3.y + bias.w);
        *(float4*)&Cout[r0 * GG + bn0 + tx * 4] = v0;
        *(float4*)&Cout[(r0 + 1) * GG + bn0 + tx * 4] = v1;
    }
}

// ---------------- persistent recurrence kernel -------------------------------
// 128 CTAs x 128 threads. CTA = 32 batch rows x 16 h-cols (x4 gates).
// Thread = 4 rows x 1 col, gate-pairs (i,f),(g,o) as f32x2.
// h staged row-major (vectorized). Weights (64KB) staged once.
// Barrier: store-based per-CTA release flags; each CTA's lanes 0-15 poll
// the 16 flags of its row group in parallel (no atomics, MLP-16 detect).
__global__ void __launch_bounds__(128, 1) lstm_persist(const float* __restrict__ whh,
                                                       int writeHbuf) {
    extern __shared__ float sm[];
    float* sWs = sm;                 // [256][64]  sWs[k*64 + hcol*4 + gate]
    float* sAs = sm + 256 * 64;      // [32][260]  h row-major, padded stride

    const int tid  = threadIdx.x;
    const int bid  = blockIdx.x;
    const int hcol = tid & 15;
    const int rq   = tid >> 4;               // 0..7
    const int c0   = (bid & 15) * 16;        // h-col group
    const int grp  = bid >> 4;               // row group 0..7
    const int bm   = grp * 32;               // batch rows
    const int col  = c0 + hcol;

    // one-time weight stage: 64 gate-rows (hcol*4+g) x 256 k
    for (int i = tid; i < 64 * 64; i += 128) {
        int lr = i >> 6;              // 0..63 local row
        int kk = (i & 63) * 4;        // k0
        int bh = lr >> 2, g = lr & 3;
        float4 v = *(const float4*)&whh[(size_t)(g * HH + c0 + bh) * HH + kk];
        sWs[(kk + 0) * 64 + lr] = v.x;
        sWs[(kk + 1) * 64 + lr] = v.y;
        sWs[(kk + 2) * 64 + lr] = v.z;
        sWs[(kk + 3) * 64 + lr] = v.w;
    }

    float creg[4] = {0.f, 0.f, 0.f, 0.f};
    int rows[4];
    #pragma unroll
    for (int r = 0; r < 4; r++) rows[r] = bm + rq * 4 + r;

    // t=0 pregate prefetch (GX layout [b][t][gate])
    float pg_i[4], pg_f[4], pg_g[4], pg_o[4];
    #pragma unroll
    for (int r = 0; r < 4; r++) {
        size_t base = (size_t)rows[r] * TT * GG + col;   // t=0
        pg_i[r] = g_GX[base];
        pg_f[r] = g_GX[base + 256];
        pg_g[r] = g_GX[base + 512];
        pg_o[r] = g_GX[base + 768];
    }

    const int sr  = tid & 31;          // staging row 0..31
    const int skc = tid >> 5;          // staging k-chunk 0..3 (64 k each)

    unsigned int* myflag = &g_flag[bid * 32];
    const unsigned int* pollflag = &g_flag[(grp * 16 + hcol) * 32];

    __syncthreads();   // weights staged

    for (int t = 0; t < TT; t++) {
        const float* __restrict__ hin  = (t & 1) ? g_H1 : g_H0;
        float* __restrict__       hout = (t & 1) ? g_H0 : g_H1;

        ull aif[4] = {0, 0, 0, 0};
        ull ago[4] = {0, 0, 0, 0};

        if (t > 0) {   // h == 0 at t=0, recurrent term vanishes
            // stage hin (32 rows x 256 k) row-major, vectorized
            {
                const float* hrow = &hin[(bm + sr) * HH + skc * 64];
                float* dst = &sAs[sr * 260 + skc * 64];
                #pragma unroll
                for (int j = 0; j < 16; j++)
                    *(float4*)&dst[j * 4] = *(const float4*)&hrow[j * 4];
            }
            __syncthreads();

            const float* hr0 = &sAs[(rq * 4 + 0) * 260];
            const float* hr1 = &sAs[(rq * 4 + 1) * 260];
            const float* hr2 = &sAs[(rq * 4 + 2) * 260];
            const float* hr3 = &sAs[(rq * 4 + 3) * 260];
            const float* bp  = &sWs[hcol * 4];

            #pragma unroll 4
            for (int k4 = 0; k4 < 256; k4 += 4) {
                float hv0[4], hv1[4], hv2[4], hv3[4];
                *(float4*)hv0 = *(const float4*)&hr0[k4];
                *(float4*)hv1 = *(const float4*)&hr1[k4];
                *(float4*)hv2 = *(const float4*)&hr2[k4];
                *(float4*)hv3 = *(const float4*)&hr3[k4];
                #pragma unroll
                for (int j = 0; j < 4; j++) {
                    ulonglong2 wv = *(const ulonglong2*)(bp + (k4 + j) * 64);
                    ull a0 = pack2(hv0[j], hv0[j]);
                    ull a1 = pack2(hv1[j], hv1[j]);
                    ull a2 = pack2(hv2[j], hv2[j]);
                    ull a3 = pack2(hv3[j], hv3[j]);
                    aif[0] = ffma2x(a0, wv.x, aif[0]);
                    ago[0] = ffma2x(a0, wv.y, ago[0]);
                    aif[1] = ffma2x(a1, wv.x, aif[1]);
                    ago[1] = ffma2x(a1, wv.y, ago[1]);
                    aif[2] = ffma2x(a2, wv.x, aif[2]);
                    ago[2] = ffma2x(a2, wv.y, ago[2]);
                    aif[3] = ffma2x(a3, wv.x, aif[3]);
                    ago[3] = ffma2x(a3, wv.y, ago[3]);
                }
            }
        }

        #pragma unroll
        for (int r = 0; r < 4; r++) {
            float2 fif = unpack2(aif[r]);
            float2 fgo = unpack2(ago[r]);
            float si = fsigm(fif.x + pg_i[r]);
            float sf = fsigm(fif.y + pg_f[r]);
            float tg = ftanh(fgo.x + pg_g[r]);
            float so = fsigm(fgo.y + pg_o[r]);
            float c  = sf * creg[r] + si * tg;
            creg[r]  = c;
            float h  = so * ftanh(c);
            hout[rows[r] * HH + col] = h;
            if (writeHbuf)
                g_HBUF[((size_t)rows[r] * TT + t) * HH + col] = h;
        }

        // ---- store-based group barrier (16 CTAs per row group) ----
        if (t < TT - 1) {
            __syncthreads();       // sAs reads done + h stores issued, all threads
            if (tid == 0) {
                __threadfence();   // make CTA's h stores GPU-visible
                st_release_u(myflag, (unsigned)(t + 1));
            }
            // prefetch next step's pregates into registers while peers arrive
            #pragma unroll
            for (int r = 0; r < 4; r++) {
                size_t base = ((size_t)rows[r] * TT + (t + 1)) * GG + col;
                pg_i[r] = g_GX[base];
                pg_f[r] = g_GX[base + 256];
                pg_g[r] = g_GX[base + 512];
                pg_o[r] = g_GX[base + 768];
            }
            if (tid < 16) {
                while (ld_acquire_u(pollflag) < (unsigned)(t + 1)) { }
            }
            __syncthreads();
        }
    }
}

// ---------------- FC + log_softmax ------------------------------------------
__global__ void __launch_bounds__(128) fc_kernel(const float* __restrict__ wfc,
                                                 const float* __restrict__ bfc,
                                                 float* __restrict__ out) {
    const int b = blockIdx.x;
    const int tid = threadIdx.x;  // 128 = one class per thread
    __shared__ float h[256];
    // t = TT-1 = 511 (odd) -> final hout = g_H0
    h[tid] = g_H0[b * HH + tid];
    h[tid + 128] = g_H0[b * HH + tid + 128];
    __syncthreads();

    float acc = bfc[tid];
    const float* wp = wfc + (size_t)tid * HH;
    #pragma unroll 8
    for (int k = 0; k < 256; k++) acc += h[k] * wp[k];

    float m = acc;
    #pragma unroll
    for (int o = 16; o > 0; o >>= 1)
        m = fmaxf(m, __shfl_xor_sync(0xffffffffu, m, o));
    __shared__ float smax[4], ssum[4];
    int wid = tid >> 5, lane = tid & 31;
    if (lane == 0) smax[wid] = m;
    __syncthreads();
    m = fmaxf(fmaxf(smax[0], smax[1]), fmaxf(smax[2], smax[3]));

    float e = expf(acc - m);
    float s = e;
    #pragma unroll
    for (int o = 16; o > 0; o >>= 1)
        s += __shfl_xor_sync(0xffffffffu, s, o);
    if (lane == 0) ssum[wid] = s;
    __syncthreads();
    s = ssum[0] + ssum[1] + ssum[2] + ssum[3];

    out[b * CC + tid] = acc - m - logf(s);
}

// ---------------- launch ------------------------------------------------------
extern "C" void kernel_launch(void* const* d_in, const int* in_sizes, int n_in,
                              void* d_out, int out_size) {
    const float* x    = (const float*)d_in[0];
    const float* wih0 = (const float*)d_in[1];
    const float* whh0 = (const float*)d_in[2];
    const float* bih0 = (const float*)d_in[3];
    const float* bhh0 = (const float*)d_in[4];
    const float* wih1 = (const float*)d_in[5];
    const float* whh1 = (const float*)d_in[6];
    const float* bih1 = (const float*)d_in[7];
    const float* bhh1 = (const float*)d_in[8];
    const float* wfc  = (const float*)d_in[9];
    const float* bfc  = (const float*)d_in[10];
    float* out = (float*)d_out;

    const int persist_smem = (256 * 64 + 32 * 260) * (int)sizeof(float); // ~98.6 KB
    cudaFuncSetAttribute(lstm_persist,
                         cudaFuncAttributeMaxDynamicSharedMemorySize,
                         persist_smem);

    dim3 gemm_grid(16, 1024);   // N/64, M/128

    // 5 launches total (flag resets folded into gemm_gx)
    // Layer 0
    gemm_gx<<<gemm_grid, 256>>>(x, 1, wih0, bih0, bhh0);
    lstm_persist<<<128, 128, persist_smem>>>(whh0, 1);

    // Layer 1
    gemm_gx<<<gemm_grid, 256>>>(nullptr, 0, wih1, bih1, bhh1);
    lstm_persist<<<128, 128, persist_smem>>>(whh1, 0);

    // Head
    fc_kernel<<<256, 128>>>(wfc, bfc, out);
}

// round 12
// speedup vs baseline: 1.1234x; 1.1234x over previous
#include <cuda_runtime.h>
#include <cuda_bf16.h>
#include <math.h>

typedef unsigned long long ull;

// Problem constants
#define BB   256          // batch
#define TT   512          // seq len
#define HH   256          // hidden
#define GG   1024         // 4*H gates
#define CC   128          // classes
#define MM   (BB*TT)      // 131072 rows for input GEMMs

// ---------------- scratch (device globals; no allocs allowed) ----------------
__device__ float g_GX[(size_t)MM * GG];      // 512 MB  pregates, layout [b][t][gate]
__device__ float g_HBUF[(size_t)MM * HH];    // 128 MB  layer-0 hidden states
__device__ float g_H0[BB * HH];
__device__ float g_H1[BB * HH];
__device__ unsigned int g_bar2[8 * 32];      // per-row-group barrier counters (128B apart)

// ---------------- packed f32x2 helpers (Blackwell FFMA2 path) ----------------
__device__ __forceinline__ ull pack2(float x, float y) {
    ull r;
    asm("mov.b64 %0, {%1, %2};" : "=l"(r) : "f"(x), "f"(y));
    return r;
}
__device__ __forceinline__ float2 unpack2(ull v) {
    float2 r;
    asm("mov.b64 {%0, %1}, %2;" : "=f"(r.x), "=f"(r.y) : "l"(v));
    return r;
}
__device__ __forceinline__ ull ffma2x(ull a, ull b, ull c) {
    ull d;
    asm("fma.rn.f32x2 %0, %1, %2, %3;" : "=l"(d) : "l"(a), "l"(b), "l"(c));
    return d;
}

// fast activations (error ~1e-6, well inside 1e-3 budget)
__device__ __forceinline__ float fsigm(float x) {
    float e = __expf(-x);
    return __fdividef(1.0f, 1.0f + e);
}
__device__ __forceinline__ float ftanh(float x) {
    float e = __expf(2.0f * x);           // overflow -> inf -> result 1 (correct)
    return 1.0f - __fdividef(2.0f, e + 1.0f);
}

__device__ __forceinline__ unsigned int ld_acquire_u(const unsigned int* p) {
    unsigned int v;
    asm volatile("ld.global.acquire.gpu.u32 %0, [%1];" : "=r"(v) : "l"(p) : "memory");
    return v;
}

// ---------------- big GEMM:  Cout[m,n] = sum_k A[m,k]*W[n,k] + b1[n] + b2[n] --
// EXACT R10 version (measured best: 1.45ms, fma 59.2%), plus a folded
// barrier-flag reset in block (0,0) so no separate reset launch is needed.
__global__ void __launch_bounds__(256) gemm_gx(const float* __restrict__ Aext,
                                               int useExt,
                                               const float* __restrict__ W,
                                               const float* __restrict__ b1,
                                               const float* __restrict__ b2) {
    __shared__ __align__(16) float As[2][16][128];
    __shared__ __align__(16) float Bs[2][16][64];

    const int tid = threadIdx.x;

    // fold barrier reset into this kernel (stream order guarantees completion
    // before lstm_persist launches)
    if (blockIdx.x == 0 && blockIdx.y == 0 && tid < 8 * 32)
        g_bar2[tid] = 0u;

    const float* __restrict__ A = useExt ? Aext : g_HBUF;
    float* __restrict__ Cout = g_GX;

    const int ty = tid >> 4;          // 0..15  (m group of 8)
    const int tx = tid & 15;          // 0..15  (n group of 4)
    const int bm0 = blockIdx.y * 128;
    const int bn0 = blockIdx.x * 64;

    const int a_row0 = tid >> 2;              // 0..63
    const int a_kg   = (tid & 3) * 4;
    const int b_row  = tid >> 2;
    const int b_kg   = (tid & 3) * 4;

    ull acc[4][4];
    #pragma unroll
    for (int i = 0; i < 4; i++)
        #pragma unroll
        for (int j = 0; j < 4; j++) acc[i][j] = 0ull;

    {
        #pragma unroll
        for (int i = 0; i < 2; i++) {
            int row = a_row0 + i * 64;
            float4 v = *(const float4*)&A[(size_t)(bm0 + row) * 256 + a_kg];
            As[0][a_kg + 0][row] = v.x; As[0][a_kg + 1][row] = v.y;
            As[0][a_kg + 2][row] = v.z; As[0][a_kg + 3][row] = v.w;
        }
        float4 v = *(const float4*)&W[(size_t)(bn0 + b_row) * 256 + b_kg];
        Bs[0][b_kg + 0][b_row] = v.x; Bs[0][b_kg + 1][b_row] = v.y;
        Bs[0][b_kg + 2][b_row] = v.z; Bs[0][b_kg + 3][b_row] = v.w;
    }
    __syncthreads();

    int buf = 0;
    for (int k0 = 0; k0 < 256; k0 += 16) {
        float4 pa0, pa1, pb;
        const bool more = (k0 + 16) < 256;
        if (more) {
            pa0 = *(const float4*)&A[(size_t)(bm0 + a_row0) * 256 + k0 + 16 + a_kg];
            pa1 = *(const float4*)&A[(size_t)(bm0 + a_row0 + 64) * 256 + k0 + 16 + a_kg];
            pb  = *(const float4*)&W[(size_t)(bn0 + b_row) * 256 + k0 + 16 + b_kg];
        }

        #pragma unroll
        for (int k = 0; k < 16; k++) {
            const ull* ap = (const ull*)&As[buf][k][ty * 8];
            ull a0 = ap[0], a1 = ap[1], a2 = ap[2], a3 = ap[3];
            float4 bv = *(const float4*)&Bs[buf][k][tx * 4];
            ull bb0 = pack2(bv.x, bv.x);
            ull bb1 = pack2(bv.y, bv.y);
            ull bb2 = pack2(bv.z, bv.z);
            ull bb3 = pack2(bv.w, bv.w);
            acc[0][0] = ffma2x(a0, bb0, acc[0][0]);
            acc[1][0] = ffma2x(a1, bb0, acc[1][0]);
            acc[2][0] = ffma2x(a2, bb0, acc[2][0]);
            acc[3][0] = ffma2x(a3, bb0, acc[3][0]);
            acc[0][1] = ffma2x(a0, bb1, acc[0][1]);
            acc[1][1] = ffma2x(a1, bb1, acc[1][1]);
            acc[2][1] = ffma2x(a2, bb1, acc[2][1]);
            acc[3][1] = ffma2x(a3, bb1, acc[3][1]);
            acc[0][2] = ffma2x(a0, bb2, acc[0][2]);
            acc[1][2] = ffma2x(a1, bb2, acc[1][2]);
            acc[2][2] = ffma2x(a2, bb2, acc[2][2]);
            acc[3][2] = ffma2x(a3, bb2, acc[3][2]);
            acc[0][3] = ffma2x(a0, bb3, acc[0][3]);
            acc[1][3] = ffma2x(a1, bb3, acc[1][3]);
            acc[2][3] = ffma2x(a2, bb3, acc[2][3]);
            acc[3][3] = ffma2x(a3, bb3, acc[3][3]);
        }

        if (more) {
            int nb = buf ^ 1;
            As[nb][a_kg + 0][a_row0] = pa0.x; As[nb][a_kg + 1][a_row0] = pa0.y;
            As[nb][a_kg + 2][a_row0] = pa0.z; As[nb][a_kg + 3][a_row0] = pa0.w;
            As[nb][a_kg + 0][a_row0 + 64] = pa1.x; As[nb][a_kg + 1][a_row0 + 64] = pa1.y;
            As[nb][a_kg + 2][a_row0 + 64] = pa1.z; As[nb][a_kg + 3][a_row0 + 64] = pa1.w;
            Bs[nb][b_kg + 0][b_row] = pb.x; Bs[nb][b_kg + 1][b_row] = pb.y;
            Bs[nb][b_kg + 2][b_row] = pb.z; Bs[nb][b_kg + 3][b_row] = pb.w;
            __syncthreads();
            buf = nb;
        }
    }

    float4 b1v = *(const float4*)&b1[bn0 + tx * 4];
    float4 b2v = *(const float4*)&b2[bn0 + tx * 4];
    float4 bias = make_float4(b1v.x + b2v.x, b1v.y + b2v.y,
                              b1v.z + b2v.z, b1v.w + b2v.w);
    #pragma unroll
    for (int i = 0; i < 4; i++) {
        float2 q0 = unpack2(acc[i][0]);
        float2 q1 = unpack2(acc[i][1]);
        float2 q2 = unpack2(acc[i][2]);
        float2 q3 = unpack2(acc[i][3]);
        size_t r0 = (size_t)(bm0 + ty * 8 + 2 * i);
        float4 v0 = make_float4(q0.x + bias.x, q1.x + bias.y, q2.x + bias.z, q3.x + bias.w);
        float4 v1 = make_float4(q0.y + bias.x, q1.y + bias.y, q2.y + bias.z, q3.y + bias.w);
        *(float4*)&Cout[r0 * GG + bn0 + tx * 4] = v0;
        *(float4*)&Cout[(r0 + 1) * GG + bn0 + tx * 4] = v1;
    }
}

// ---------------- persistent recurrence kernel -------------------------------
// 128 CTAs x 256 threads (2 warps/SMSP to hide LDS latency — R11 profile
// showed issue=21% at 1 warp/SMSP). CTA = 32 batch rows x 16 h-cols
// (x4 gates). Thread = 2 rows x 1 col; gate-pairs (i,f),(g,o) as f32x2.
// Same smem layouts and same atomic group barrier as R10 (measured best).
__global__ void __launch_bounds__(256, 1) lstm_persist(const float* __restrict__ whh,
                                                       int writeHbuf) {
    extern __shared__ float sm[];
    float* sWs = sm;                 // [256][64]  sWs[k*64 + hcol*4 + gate]
    float* sAs = sm + 256 * 64;      // [32][260]  h row-major, padded stride

    const int tid  = threadIdx.x;
    const int bid  = blockIdx.x;
    const int hcol = tid & 15;
    const int rq   = tid >> 4;               // 0..15
    const int c0   = (bid & 15) * 16;        // h-col group
    const int grp  = bid >> 4;               // row group 0..7
    const int bm   = grp * 32;               // batch rows
    const int col  = c0 + hcol;

    // one-time weight stage: 64 gate-rows (hcol*4+g) x 256 k
    for (int i = tid; i < 64 * 64; i += 256) {
        int lr = i >> 6;              // 0..63 local row
        int kk = (i & 63) * 4;        // k0
        int bh = lr >> 2, g = lr & 3;
        float4 v = *(const float4*)&whh[(size_t)(g * HH + c0 + bh) * HH + kk];
        sWs[(kk + 0) * 64 + lr] = v.x;
        sWs[(kk + 1) * 64 + lr] = v.y;
        sWs[(kk + 2) * 64 + lr] = v.z;
        sWs[(kk + 3) * 64 + lr] = v.w;
    }
    __syncthreads();

    float creg[2] = {0.f, 0.f};
    int rows[2];
    rows[0] = bm + rq * 2;
    rows[1] = bm + rq * 2 + 1;

    // t=0 pregate prefetch (GX layout [b][t][gate])
    float pg_i[2], pg_f[2], pg_g[2], pg_o[2];
    #pragma unroll
    for (int r = 0; r < 2; r++) {
        size_t base = (size_t)rows[r] * TT * GG + col;   // t=0
        pg_i[r] = g_GX[base];
        pg_f[r] = g_GX[base + 256];
        pg_g[r] = g_GX[base + 512];
        pg_o[r] = g_GX[base + 768];
    }

    const int sr  = tid & 31;          // staging row 0..31
    const int skc = tid >> 5;          // staging k-chunk 0..7 (32 k each)

    unsigned int* barp = &g_bar2[grp * 32];

    for (int t = 0; t < TT; t++) {
        const float* __restrict__ hin  = (t & 1) ? g_H1 : g_H0;
        float* __restrict__       hout = (t & 1) ? g_H0 : g_H1;

        ull aif[2] = {0, 0};
        ull ago[2] = {0, 0};

        if (t > 0) {   // h == 0 at t=0, recurrent term vanishes
            // stage hin (32 rows x 256 k) row-major, vectorized
            {
                const float* hrow = &hin[(bm + sr) * HH + skc * 32];
                float* dst = &sAs[sr * 260 + skc * 32];
                #pragma unroll
                for (int j = 0; j < 8; j++)
                    *(float4*)&dst[j * 4] = *(const float4*)&hrow[j * 4];
            }
            __syncthreads();

            const float* hr0 = &sAs[(rq * 2 + 0) * 260];
            const float* hr1 = &sAs[(rq * 2 + 1) * 260];
            const float* bp  = &sWs[hcol * 4];

            #pragma unroll 4
            for (int k4 = 0; k4 < 256; k4 += 4) {
                float hv0[4], hv1[4];
                *(float4*)hv0 = *(const float4*)&hr0[k4];
                *(float4*)hv1 = *(const float4*)&hr1[k4];
                #pragma unroll
                for (int j = 0; j < 4; j++) {
                    ulonglong2 wv = *(const ulonglong2*)(bp + (k4 + j) * 64);
                    ull a0 = pack2(hv0[j], hv0[j]);
                    ull a1 = pack2(hv1[j], hv1[j]);
                    aif[0] = ffma2x(a0, wv.x, aif[0]);
                    ago[0] = ffma2x(a0, wv.y, ago[0]);
                    aif[1] = ffma2x(a1, wv.x, aif[1]);
                    ago[1] = ffma2x(a1, wv.y, ago[1]);
                }
            }
            __syncthreads();   // sAs re-staged next step
        }

        #pragma unroll
        for (int r = 0; r < 2; r++) {
            float2 fif = unpack2(aif[r]);
            float2 fgo = unpack2(ago[r]);
            float si = fsigm(fif.x + pg_i[r]);
            float sf = fsigm(fif.y + pg_f[r]);
            float tg = ftanh(fgo.x + pg_g[r]);
            float so = fsigm(fgo.y + pg_o[r]);
            float c  = sf * creg[r] + si * tg;
            creg[r]  = c;
            float h  = so * ftanh(c);
            hout[rows[r] * HH + col] = h;
            if (writeHbuf)
                g_HBUF[((size_t)rows[r] * TT + t) * HH + col] = h;
        }

        // ---- per-row-group barrier (16 CTAs per counter) ----
        if (t < TT - 1) {
            __syncthreads();                       // all h stores issued
            if (tid == 0) {
                __threadfence();                   // release h to GPU scope
                atomicAdd(barp, 1u);
            }
            // prefetch next step's pregates into registers while peers arrive
            #pragma unroll
            for (int r = 0; r < 2; r++) {
                size_t base = ((size_t)rows[r] * TT + (t + 1)) * GG + col;
                pg_i[r] = g_GX[base];
                pg_f[r] = g_GX[base + 256];
                pg_g[r] = g_GX[base + 512];
                pg_o[r] = g_GX[base + 768];
            }
            if (tid == 0) {
                unsigned target = (unsigned)(t + 1) * 16u;
                while (ld_acquire_u(barp) < target) { }
            }
            __syncthreads();
        }
    }
}

// ---------------- FC + log_softmax ------------------------------------------
__global__ void __launch_bounds__(128) fc_kernel(const float* __restrict__ wfc,
                                                 const float* __restrict__ bfc,
                                                 float* __restrict__ out) {
    const int b = blockIdx.x;
    const int tid = threadIdx.x;  // 128 = one class per thread
    __shared__ float h[256];
    // t = TT-1 = 511 (odd) -> final hout = g_H0
    h[tid] = g_H0[b * HH + tid];
    h[tid + 128] = g_H0[b * HH + tid + 128];
    __syncthreads();

    float acc = bfc[tid];
    const float* wp = wfc + (size_t)tid * HH;
    #pragma unroll 8
    for (int k = 0; k < 256; k++) acc += h[k] * wp[k];

    float m = acc;
    #pragma unroll
    for (int o = 16; o > 0; o >>= 1)
        m = fmaxf(m, __shfl_xor_sync(0xffffffffu, m, o));
    __shared__ float smax[4], ssum[4];
    int wid = tid >> 5, lane = tid & 31;
    if (lane == 0) smax[wid] = m;
    __syncthreads();
    m = fmaxf(fmaxf(smax[0], smax[1]), fmaxf(smax[2], smax[3]));

    float e = expf(acc - m);
    float s = e;
    #pragma unroll
    for (int o = 16; o > 0; o >>= 1)
        s += __shfl_xor_sync(0xffffffffu, s, o);
    if (lane == 0) ssum[wid] = s;
    __syncthreads();
    s = ssum[0] + ssum[1] + ssum[2] + ssum[3];

    out[b * CC + tid] = acc - m - logf(s);
}

// ---------------- launch ------------------------------------------------------
extern "C" void kernel_launch(void* const* d_in, const int* in_sizes, int n_in,
                              void* d_out, int out_size) {
    const float* x    = (const float*)d_in[0];
    const float* wih0 = (const float*)d_in[1];
    const float* whh0 = (const float*)d_in[2];
    const float* bih0 = (const float*)d_in[3];
    const float* bhh0 = (const float*)d_in[4];
    const float* wih1 = (const float*)d_in[5];
    const float* whh1 = (const float*)d_in[6];
    const float* bih1 = (const float*)d_in[7];
    const float* bhh1 = (const float*)d_in[8];
    const float* wfc  = (const float*)d_in[9];
    const float* bfc  = (const float*)d_in[10];
    float* out = (float*)d_out;

    const int persist_smem = (256 * 64 + 32 * 260) * (int)sizeof(float); // ~98.6 KB
    cudaFuncSetAttribute(lstm_persist,
                         cudaFuncAttributeMaxDynamicSharedMemorySize,
                         persist_smem);

    dim3 gemm_grid(16, 1024);   // N/64, M/128

    // 5 launches total (barrier reset folded into gemm_gx)
    // Layer 0
    gemm_gx<<<gemm_grid, 256>>>(x, 1, wih0, bih0, bhh0);
    lstm_persist<<<128, 256, persist_smem>>>(whh0, 1);

    // Layer 1
    gemm_gx<<<gemm_grid, 256>>>(nullptr, 0, wih1, bih1, bhh1);
    lstm_persist<<<128, 256, persist_smem>>>(whh1, 0);

    // Head
    fc_kernel<<<256, 128>>>(wfc, bfc, out);
}

// round 13
// speedup vs baseline: 1.2736x; 1.1337x over previous
#include <cuda_runtime.h>
#include <cuda_bf16.h>
#include <math.h>

typedef unsigned long long ull;

// Problem constants
#define BB   256          // batch
#define TT   512          // seq len
#define HH   256          // hidden
#define GG   1024         // 4*H gates
#define CC   128          // classes
#define MM   (BB*TT)      // 131072 rows for input GEMM

// ---------------- scratch (device globals; no allocs allowed) ----------------
__device__ float g_GX [(size_t)MM * GG];     // 512 MB layer-0 pregates [b][t][gate]
__device__ float g_GX1[(size_t)MM * GG];     // 512 MB layer-1 pregates [b][t][gate]
__device__ float g_H0[BB * HH];
__device__ float g_H1[BB * HH];
__device__ unsigned int g_bars[2][8 * 32];   // per-layer, per-row-group counters

// ---------------- packed f32x2 helpers (Blackwell FFMA2 path) ----------------
__device__ __forceinline__ ull pack2(float x, float y) {
    ull r;
    asm("mov.b64 %0, {%1, %2};" : "=l"(r) : "f"(x), "f"(y));
    return r;
}
__device__ __forceinline__ float2 unpack2(ull v) {
    float2 r;
    asm("mov.b64 {%0, %1}, %2;" : "=f"(r.x), "=f"(r.y) : "l"(v));
    return r;
}
__device__ __forceinline__ ull ffma2x(ull a, ull b, ull c) {
    ull d;
    asm("fma.rn.f32x2 %0, %1, %2, %3;" : "=l"(d) : "l"(a), "l"(b), "l"(c));
    return d;
}

// fast activations (error ~1e-6, well inside 1e-3 budget)
__device__ __forceinline__ float fsigm(float x) {
    float e = __expf(-x);
    return __fdividef(1.0f, 1.0f + e);
}
__device__ __forceinline__ float ftanh(float x) {
    float e = __expf(2.0f * x);           // overflow -> inf -> result 1 (correct)
    return 1.0f - __fdividef(2.0f, e + 1.0f);
}

__device__ __forceinline__ unsigned int ld_acquire_u(const unsigned int* p) {
    unsigned int v;
    asm volatile("ld.global.acquire.gpu.u32 %0, [%1];" : "=r"(v) : "l"(p) : "memory");
    return v;
}

// ---------------- big GEMM (layer-0 pregates only) ----------------------------
// g_GX[m,n] = sum_k x[m,k]*W[n,k] + b1[n] + b2[n].  EXACT R10 structure
// (measured best 1.45ms, fma 59%), plus folded reset of BOTH layers' flags.
__global__ void __launch_bounds__(256) gemm_gx(const float* __restrict__ A,
                                               const float* __restrict__ W,
                                               const float* __restrict__ b1,
                                               const float* __restrict__ b2) {
    __shared__ __align__(16) float As[2][16][128];
    __shared__ __align__(16) float Bs[2][16][64];

    const int tid = threadIdx.x;

    // reset barrier flags for both persist launches (stream order guarantees
    // this kernel completes before they start)
    if (blockIdx.x == 0 && blockIdx.y == 0) {
        g_bars[0][tid] = 0u;
        g_bars[1][tid] = 0u;
    }

    float* __restrict__ Cout = g_GX;

    const int ty = tid >> 4;          // 0..15  (m group of 8)
    const int tx = tid & 15;          // 0..15  (n group of 4)
    const int bm0 = blockIdx.y * 128;
    const int bn0 = blockIdx.x * 64;

    const int a_row0 = tid >> 2;              // 0..63
    const int a_kg   = (tid & 3) * 4;
    const int b_row  = tid >> 2;
    const int b_kg   = (tid & 3) * 4;

    ull acc[4][4];
    #pragma unroll
    for (int i = 0; i < 4; i++)
        #pragma unroll
        for (int j = 0; j < 4; j++) acc[i][j] = 0ull;

    {
        #pragma unroll
        for (int i = 0; i < 2; i++) {
            int row = a_row0 + i * 64;
            float4 v = *(const float4*)&A[(size_t)(bm0 + row) * 256 + a_kg];
            As[0][a_kg + 0][row] = v.x; As[0][a_kg + 1][row] = v.y;
            As[0][a_kg + 2][row] = v.z; As[0][a_kg + 3][row] = v.w;
        }
        float4 v = *(const float4*)&W[(size_t)(bn0 + b_row) * 256 + b_kg];
        Bs[0][b_kg + 0][b_row] = v.x; Bs[0][b_kg + 1][b_row] = v.y;
        Bs[0][b_kg + 2][b_row] = v.z; Bs[0][b_kg + 3][b_row] = v.w;
    }
    __syncthreads();

    int buf = 0;
    for (int k0 = 0; k0 < 256; k0 += 16) {
        float4 pa0, pa1, pb;
        const bool more = (k0 + 16) < 256;
        if (more) {
            pa0 = *(const float4*)&A[(size_t)(bm0 + a_row0) * 256 + k0 + 16 + a_kg];
            pa1 = *(const float4*)&A[(size_t)(bm0 + a_row0 + 64) * 256 + k0 + 16 + a_kg];
            pb  = *(const float4*)&W[(size_t)(bn0 + b_row) * 256 + k0 + 16 + b_kg];
        }

        #pragma unroll
        for (int k = 0; k < 16; k++) {
            const ull* ap = (const ull*)&As[buf][k][ty * 8];
            ull a0 = ap[0], a1 = ap[1], a2 = ap[2], a3 = ap[3];
            float4 bv = *(const float4*)&Bs[buf][k][tx * 4];
            ull bb0 = pack2(bv.x, bv.x);
            ull bb1 = pack2(bv.y, bv.y);
            ull bb2 = pack2(bv.z, bv.z);
            ull bb3 = pack2(bv.w, bv.w);
            acc[0][0] = ffma2x(a0, bb0, acc[0][0]);
            acc[1][0] = ffma2x(a1, bb0, acc[1][0]);
            acc[2][0] = ffma2x(a2, bb0, acc[2][0]);
            acc[3][0] = ffma2x(a3, bb0, acc[3][0]);
            acc[0][1] = ffma2x(a0, bb1, acc[0][1]);
            acc[1][1] = ffma2x(a1, bb1, acc[1][1]);
            acc[2][1] = ffma2x(a2, bb1, acc[2][1]);
            acc[3][1] = ffma2x(a3, bb1, acc[3][1]);
            acc[0][2] = ffma2x(a0, bb2, acc[0][2]);
            acc[1][2] = ffma2x(a1, bb2, acc[1][2]);
            acc[2][2] = ffma2x(a2, bb2, acc[2][2]);
            acc[3][2] = ffma2x(a3, bb2, acc[3][2]);
            acc[0][3] = ffma2x(a0, bb3, acc[0][3]);
            acc[1][3] = ffma2x(a1, bb3, acc[1][3]);
            acc[2][3] = ffma2x(a2, bb3, acc[2][3]);
            acc[3][3] = ffma2x(a3, bb3, acc[3][3]);
        }

        if (more) {
            int nb = buf ^ 1;
            As[nb][a_kg + 0][a_row0] = pa0.x; As[nb][a_kg + 1][a_row0] = pa0.y;
            As[nb][a_kg + 2][a_row0] = pa0.z; As[nb][a_kg + 3][a_row0] = pa0.w;
            As[nb][a_kg + 0][a_row0 + 64] = pa1.x; As[nb][a_kg + 1][a_row0 + 64] = pa1.y;
            As[nb][a_kg + 2][a_row0 + 64] = pa1.z; As[nb][a_kg + 3][a_row0 + 64] = pa1.w;
            Bs[nb][b_kg + 0][b_row] = pb.x; Bs[nb][b_kg + 1][b_row] = pb.y;
            Bs[nb][b_kg + 2][b_row] = pb.z; Bs[nb][b_kg + 3][b_row] = pb.w;
            __syncthreads();
            buf = nb;
        }
    }

    float4 b1v = *(const float4*)&b1[bn0 + tx * 4];
    float4 b2v = *(const float4*)&b2[bn0 + tx * 4];
    float4 bias = make_float4(b1v.x + b2v.x, b1v.y + b2v.y,
                              b1v.z + b2v.z, b1v.w + b2v.w);
    #pragma unroll
    for (int i = 0; i < 4; i++) {
        float2 q0 = unpack2(acc[i][0]);
        float2 q1 = unpack2(acc[i][1]);
        float2 q2 = unpack2(acc[i][2]);
        float2 q3 = unpack2(acc[i][3]);
        size_t r0 = (size_t)(bm0 + ty * 8 + 2 * i);
        float4 v0 = make_float4(q0.x + bias.x, q1.x + bias.y, q2.x + bias.z, q3.x + bias.w);
        float4 v1 = make_float4(q0.y + bias.x, q1.y + bias.y, q2.y + bias.z, q3.y + bias.w);
        *(float4*)&Cout[r0 * GG + bn0 + tx * 4] = v0;
        *(float4*)&Cout[(r0 + 1) * GG + bn0 + tx * 4] = v1;
    }
}

// ---------------- persistent recurrence (+ fused next-layer input GEMM) ------
// 128 CTAs x 128 threads (R10 measured-best shape). CTA = 32 rows x 16 cols.
// Layer 0 (hasWih=1): while the recurrent k-loop runs on sAs = h0[t-1], the
// SAME staged operand also feeds gx1[t-1] = h0[t-1] @ Wih1^T + biases, stored
// to g_GX1 — this replaces the entire layer-1 input GEMM launch. A tail
// phase (t == TT) produces gx1[511].
__global__ void __launch_bounds__(128, 1) lstm_persist(const float* __restrict__ whh,
                                                       const float* __restrict__ wih,
                                                       const float* __restrict__ bi1,
                                                       const float* __restrict__ bh1,
                                                       int layer) {
    extern __shared__ float sm[];
    float* sWs = sm;                 // [256][64]  Whh slice  [k][hcol*4+g]
    float* sWi = sm + 256 * 64;      // [256][64]  Wih1 slice [k][hcol*4+g]
    float* sAs = sm + 2 * 256 * 64;  // [32][260]  h row-major, padded

    const int hasWih = (layer == 0);
    const float* __restrict__ gxin = hasWih ? g_GX : g_GX1;

    const int tid  = threadIdx.x;
    const int bid  = blockIdx.x;
    const int hcol = tid & 15;
    const int rq   = tid >> 4;               // 0..7
    const int c0   = (bid & 15) * 16;        // h-col group
    const int grp  = bid >> 4;               // row group 0..7
    const int bm   = grp * 32;               // batch rows
    const int col  = c0 + hcol;

    // one-time weight stage: Whh slice (and Wih1 slice for layer 0)
    for (int i = tid; i < 64 * 64; i += 128) {
        int lr = i >> 6;              // 0..63 local row (hcol*4+g)
        int kk = (i & 63) * 4;        // k0
        int bh = lr >> 2, g = lr & 3;
        float4 v = *(const float4*)&whh[(size_t)(g * HH + c0 + bh) * HH + kk];
        sWs[(kk + 0) * 64 + lr] = v.x;
        sWs[(kk + 1) * 64 + lr] = v.y;
        sWs[(kk + 2) * 64 + lr] = v.z;
        sWs[(kk + 3) * 64 + lr] = v.w;
        if (hasWih) {
            float4 w = *(const float4*)&wih[(size_t)(g * HH + c0 + bh) * HH + kk];
            sWi[(kk + 0) * 64 + lr] = w.x;
            sWi[(kk + 1) * 64 + lr] = w.y;
            sWi[(kk + 2) * 64 + lr] = w.z;
            sWi[(kk + 3) * 64 + lr] = w.w;
        }
    }
    __syncthreads();

    // next-layer biases for this thread's column (layer 0 only)
    float nb_i = 0.f, nb_f = 0.f, nb_g = 0.f, nb_o = 0.f;
    if (hasWih) {
        nb_i = bi1[col]       + bh1[col];
        nb_f = bi1[256 + col] + bh1[256 + col];
        nb_g = bi1[512 + col] + bh1[512 + col];
        nb_o = bi1[768 + col] + bh1[768 + col];
    }

    float creg[4] = {0.f, 0.f, 0.f, 0.f};
    int rows[4];
    #pragma unroll
    for (int r = 0; r < 4; r++) rows[r] = bm + rq * 4 + r;

    // t=0 pregate prefetch
    float pg_i[4], pg_f[4], pg_g[4], pg_o[4];
    #pragma unroll
    for (int r = 0; r < 4; r++) {
        size_t base = (size_t)rows[r] * TT * GG + col;   // t=0
        pg_i[r] = gxin[base];
        pg_f[r] = gxin[base + 256];
        pg_g[r] = gxin[base + 512];
        pg_o[r] = gxin[base + 768];
    }

    const int sr  = tid & 31;          // staging row 0..31
    const int skc = tid >> 5;          // staging k-chunk 0..3 (64 k each)

    unsigned int* barp = &g_bars[layer][grp * 32];

    const int tEnd = hasWih ? TT : (TT - 1);   // layer 0 runs a tail phase

    for (int t = 0; t <= tEnd; t++) {
        const float* __restrict__ hin  = (t & 1) ? g_H1 : g_H0;
        float* __restrict__       hout = (t & 1) ? g_H0 : g_H1;

        ull aif[4] = {0, 0, 0, 0};     // recurrent (i,f),(g,o)
        ull ago[4] = {0, 0, 0, 0};
        ull bif[4] = {0, 0, 0, 0};     // next-layer input (i,f),(g,o)
        ull bgo[4] = {0, 0, 0, 0};

        if (t > 0) {
            // stage hin (32 rows x 256 k) row-major, vectorized
            {
                const float* hrow = &hin[(bm + sr) * HH + skc * 64];
                float* dst = &sAs[sr * 260 + skc * 64];
                #pragma unroll
                for (int j = 0; j < 16; j++)
                    *(float4*)&dst[j * 4] = *(const float4*)&hrow[j * 4];
            }
            __syncthreads();

            const float* hr0 = &sAs[(rq * 4 + 0) * 260];
            const float* hr1 = &sAs[(rq * 4 + 1) * 260];
            const float* hr2 = &sAs[(rq * 4 + 2) * 260];
            const float* hr3 = &sAs[(rq * 4 + 3) * 260];
            const float* bpW = &sWs[hcol * 4];
            const float* bpI = &sWi[hcol * 4];

            if (hasWih) {
                #pragma unroll 2
                for (int k4 = 0; k4 < 256; k4 += 4) {
                    float hv0[4], hv1[4], hv2[4], hv3[4];
                    *(float4*)hv0 = *(const float4*)&hr0[k4];
                    *(float4*)hv1 = *(const float4*)&hr1[k4];
                    *(float4*)hv2 = *(const float4*)&hr2[k4];
                    *(float4*)hv3 = *(const float4*)&hr3[k4];
                    #pragma unroll
                    for (int j = 0; j < 4; j++) {
                        ulonglong2 wv = *(const ulonglong2*)(bpW + (k4 + j) * 64);
                        ulonglong2 wi = *(const ulonglong2*)(bpI + (k4 + j) * 64);
                        ull a0 = pack2(hv0[j], hv0[j]);
                        ull a1 = pack2(hv1[j], hv1[j]);
                        ull a2 = pack2(hv2[j], hv2[j]);
                        ull a3 = pack2(hv3[j], hv3[j]);
                        aif[0] = ffma2x(a0, wv.x, aif[0]);
                        ago[0] = ffma2x(a0, wv.y, ago[0]);
                        bif[0] = ffma2x(a0, wi.x, bif[0]);
                        bgo[0] = ffma2x(a0, wi.y, bgo[0]);
                        aif[1] = ffma2x(a1, wv.x, aif[1]);
                        ago[1] = ffma2x(a1, wv.y, ago[1]);
                        bif[1] = ffma2x(a1, wi.x, bif[1]);
                        bgo[1] = ffma2x(a1, wi.y, bgo[1]);
                        aif[2] = ffma2x(a2, wv.x, aif[2]);
                        ago[2] = ffma2x(a2, wv.y, ago[2]);
                        bif[2] = ffma2x(a2, wi.x, bif[2]);
                        bgo[2] = ffma2x(a2, wi.y, bgo[2]);
                        aif[3] = ffma2x(a3, wv.x, aif[3]);
                        ago[3] = ffma2x(a3, wv.y, ago[3]);
                        bif[3] = ffma2x(a3, wi.x, bif[3]);
                        bgo[3] = ffma2x(a3, wi.y, bgo[3]);
                    }
                }
            } else {
                #pragma unroll 4
                for (int k4 = 0; k4 < 256; k4 += 4) {
                    float hv0[4], hv1[4], hv2[4], hv3[4];
                    *(float4*)hv0 = *(const float4*)&hr0[k4];
                    *(float4*)hv1 = *(const float4*)&hr1[k4];
                    *(float4*)hv2 = *(const float4*)&hr2[k4];
                    *(float4*)hv3 = *(const float4*)&hr3[k4];
                    #pragma unroll
                    for (int j = 0; j < 4; j++) {
                        ulonglong2 wv = *(const ulonglong2*)(bpW + (k4 + j) * 64);
                        ull a0 = pack2(hv0[j], hv0[j]);
                        ull a1 = pack2(hv1[j], hv1[j]);
                        ull a2 = pack2(hv2[j], hv2[j]);
                        ull a3 = pack2(hv3[j], hv3[j]);
                        aif[0] = ffma2x(a0, wv.x, aif[0]);
                        ago[0] = ffma2x(a0, wv.y, ago[0]);
                        aif[1] = ffma2x(a1, wv.x, aif[1]);
                        ago[1] = ffma2x(a1, wv.y, ago[1]);
                        aif[2] = ffma2x(a2, wv.x, aif[2]);
                        ago[2] = ffma2x(a2, wv.y, ago[2]);
                        aif[3] = ffma2x(a3, wv.x, aif[3]);
                        ago[3] = ffma2x(a3, wv.y, ago[3]);
                    }
                }
            }
            __syncthreads();   // sAs re-staged next step

            // store next-layer pregates gx1[t-1] (layer 0 only)
            if (hasWih) {
                #pragma unroll
                for (int r = 0; r < 4; r++) {
                    float2 fif = unpack2(bif[r]);
                    float2 fgo = unpack2(bgo[r]);
                    size_t base = ((size_t)rows[r] * TT + (t - 1)) * GG + col;
                    g_GX1[base]       = fif.x + nb_i;
                    g_GX1[base + 256] = fif.y + nb_f;
                    g_GX1[base + 512] = fgo.x + nb_g;
                    g_GX1[base + 768] = fgo.y + nb_o;
                }
            }
        }

        if (t < TT) {
            #pragma unroll
            for (int r = 0; r < 4; r++) {
                float2 fif = unpack2(aif[r]);
                float2 fgo = unpack2(ago[r]);
                float si = fsigm(fif.x + pg_i[r]);
                float sf = fsigm(fif.y + pg_f[r]);
                float tg = ftanh(fgo.x + pg_g[r]);
                float so = fsigm(fgo.y + pg_o[r]);
                float c  = sf * creg[r] + si * tg;
                creg[r]  = c;
                float h  = so * ftanh(c);
                hout[rows[r] * HH + col] = h;
            }
        }

        // ---- per-row-group barrier (16 CTAs per counter) ----
        if (t < tEnd) {
            __syncthreads();                       // all h stores issued
            if (tid == 0) {
                __threadfence();                   // release h to GPU scope
                atomicAdd(barp, 1u);
            }
            // prefetch next step's pregates into registers while peers arrive
            if (t + 1 < TT) {
                #pragma unroll
                for (int r = 0; r < 4; r++) {
                    size_t base = ((size_t)rows[r] * TT + (t + 1)) * GG + col;
                    pg_i[r] = gxin[base];
                    pg_f[r] = gxin[base + 256];
                    pg_g[r] = gxin[base + 512];
                    pg_o[r] = gxin[base + 768];
                }
            }
            if (tid == 0) {
                unsigned target = (unsigned)(t + 1) * 16u;
                while (ld_acquire_u(barp) < target) { }
            }
            __syncthreads();
        }
    }
}

// ---------------- FC + log_softmax ------------------------------------------
__global__ void __launch_bounds__(128) fc_kernel(const float* __restrict__ wfc,
                                                 const float* __restrict__ bfc,
                                                 float* __restrict__ out) {
    const int b = blockIdx.x;
    const int tid = threadIdx.x;  // 128 = one class per thread
    __shared__ float h[256];
    // t = TT-1 = 511 (odd) -> final hout = g_H0
    h[tid] = g_H0[b * HH + tid];
    h[tid + 128] = g_H0[b * HH + tid + 128];
    __syncthreads();

    float acc = bfc[tid];
    const float* wp = wfc + (size_t)tid * HH;
    #pragma unroll 8
    for (int k = 0; k < 256; k++) acc += h[k] * wp[k];

    float m = acc;
    #pragma unroll
    for (int o = 16; o > 0; o >>= 1)
        m = fmaxf(m, __shfl_xor_sync(0xffffffffu, m, o));
    __shared__ float smax[4], ssum[4];
    int wid = tid >> 5, lane = tid & 31;
    if (lane == 0) smax[wid] = m;
    __syncthreads();
    m = fmaxf(fmaxf(smax[0], smax[1]), fmaxf(smax[2], smax[3]));

    float e = expf(acc - m);
    float s = e;
    #pragma unroll
    for (int o = 16; o > 0; o >>= 1)
        s += __shfl_xor_sync(0xffffffffu, s, o);
    if (lane == 0) ssum[wid] = s;
    __syncthreads();
    s = ssum[0] + ssum[1] + ssum[2] + ssum[3];

    out[b * CC + tid] = acc - m - logf(s);
}

// ---------------- launch ------------------------------------------------------
extern "C" void kernel_launch(void* const* d_in, const int* in_sizes, int n_in,
                              void* d_out, int out_size) {
    const float* x    = (const float*)d_in[0];
    const float* wih0 = (const float*)d_in[1];
    const float* whh0 = (const float*)d_in[2];
    const float* bih0 = (const float*)d_in[3];
    const float* bhh0 = (const float*)d_in[4];
    const float* wih1 = (const float*)d_in[5];
    const float* whh1 = (const float*)d_in[6];
    const float* bih1 = (const float*)d_in[7];
    const float* bhh1 = (const float*)d_in[8];
    const float* wfc  = (const float*)d_in[9];
    const float* bfc  = (const float*)d_in[10];
    float* out = (float*)d_out;

    const int persist_smem = (2 * 256 * 64 + 32 * 260) * (int)sizeof(float); // ~160.5 KB
    cudaFuncSetAttribute(lstm_persist,
                         cudaFuncAttributeMaxDynamicSharedMemorySize,
                         persist_smem);

    dim3 gemm_grid(16, 1024);   // N/64, M/128

    // 4 launches total: gemm0 -> persist(L0, fused gx1) -> persist(L1) -> fc
    gemm_gx<<<gemm_grid, 256>>>(x, wih0, bih0, bhh0);
    lstm_persist<<<128, 128, persist_smem>>>(whh0, wih1, bih1, bhh1, 0);
    lstm_persist<<<128, 128, persist_smem>>>(whh1, nullptr, nullptr, nullptr, 1);
    fc_kernel<<<256, 128>>>(wfc, bfc, out);
}